// round 2
// baseline (speedup 1.0000x reference)
#include <cuda_runtime.h>

// ---------------------------------------------------------------------------
// Problem constants (from reference setup_inputs; steps fixed at 30)
// ---------------------------------------------------------------------------
#define IN_DIM   1024
#define HID      2048
#define OUT_DIM  1000
#define BATCH    4096
#define STEPS    30
#define NPI      30         // power iterations
#define EPSN     1e-12f

// Power-iteration block groups (blocks per matrix)
#define G_IN  32
#define G_REC 64
#define G_OUT 32
#define NB_PI (G_IN + G_REC + G_OUT)   // 128 blocks

// ---------------------------------------------------------------------------
// Device scratch (allocation-free rule: __device__ globals)
// ---------------------------------------------------------------------------
__device__ float g_u[6144];        // raw u: in@0 (2048), rec@2048 (2048), out@4096 (1000)
__device__ float g_y[6144];        // raw y: in@0 (1024), rec@2048 (2048), out@4096 (2048)
__device__ float g_partY[3][64];   // per-block sumsq partials, phase Y
__device__ float g_partZ[3][64];   // per-block sumsq partials, phase Z
__device__ float g_sigpart[3][64]; // sigma partials
__device__ float g_inv_sigma[3];

__device__ float g_xproj[(size_t)BATCH * HID];
__device__ float g_h0[(size_t)BATCH * HID];
__device__ float g_h1[(size_t)BATCH * HID];

// ---------------------------------------------------------------------------
// Power iteration: W is [M, N] row-major (out x in).
// Reference per iter: v = norm(W^T u); u = norm(W v).
// Kernel boundaries act as grid barriers. Each block writes its own partial
// slot (plain store, no atomics -> deterministic, no reset needed).
// ---------------------------------------------------------------------------
struct PiCtx {
    int m, bg, G, M, N;
    const float* W;
    float* ubuf;
    float* ybuf;
};

__device__ __forceinline__ PiCtx pi_ctx(int b, const float* Win, const float* Wrec,
                                        const float* Wout) {
    PiCtx c;
    if (b < G_IN) {
        c.m = 0; c.bg = b;               c.G = G_IN;  c.M = HID;     c.N = IN_DIM;
        c.W = Win;  c.ubuf = g_u;        c.ybuf = g_y;
    } else if (b < G_IN + G_REC) {
        c.m = 1; c.bg = b - G_IN;        c.G = G_REC; c.M = HID;     c.N = HID;
        c.W = Wrec; c.ubuf = g_u + 2048; c.ybuf = g_y + 2048;
    } else {
        c.m = 2; c.bg = b - G_IN - G_REC; c.G = G_OUT; c.M = OUT_DIM; c.N = HID;
        c.W = Wout; c.ubuf = g_u + 4096;  c.ybuf = g_y + 4096;
    }
    return c;
}

// Init: u = ones (raw), partZ set so that su = 1/(sqrt(M)+eps) on first phaseY.
__global__ void pi_init() {
    int t = threadIdx.x;
    for (int i = t; i < 2048; i += 256) {
        g_u[i] = 1.0f;
        g_u[2048 + i] = 1.0f;
        if (i < OUT_DIM) g_u[4096 + i] = 1.0f;
    }
    if (t == 0) {
        for (int g = 0; g < 64; ++g) {
            g_partZ[0][g] = 0.0f; g_partZ[1][g] = 0.0f; g_partZ[2][g] = 0.0f;
        }
        g_partZ[0][0] = (float)HID;
        g_partZ[1][0] = (float)HID;
        g_partZ[2][0] = (float)OUT_DIM;
    }
}

// Phase Y: ybuf = W^T u_hat  (u_hat = su * ubuf, su derived from partZ).
__global__ void pi_phaseY(const float* __restrict__ Win, const float* __restrict__ Wrec,
                          const float* __restrict__ Wout) {
    PiCtx c = pi_ctx(blockIdx.x, Win, Wrec, Wout);
    float ss = 0.0f;
    for (int g = 0; g < c.G; ++g) ss += g_partZ[c.m][g];     // fixed order: deterministic
    float su = 1.0f / (sqrtf(ss) + EPSN);

    int cpb = c.N / c.G;          // cols per block: 32 / 32 / 64
    int tpc = 256 / cpb;          // threads per col: 8 / 8 / 4
    int cl  = threadIdx.x % cpb;
    int seg = threadIdx.x / cpb;
    int col = c.bg * cpb + cl;
    int rps = c.M / tpc;          // rows per segment: 256 / 256 / 250
    int r0  = seg * rps;

    float acc = 0.0f;
    const float* Wc = c.W + col;
    for (int i = r0; i < r0 + rps; ++i)
        acc += Wc[(size_t)i * c.N] * c.ubuf[i];

    __shared__ float red[256];
    __shared__ float ssq[64];
    red[threadIdx.x] = acc;
    __syncthreads();
    if (seg == 0) {
        float tot = 0.0f;
        for (int s = 0; s < tpc; ++s) tot += red[cl + s * cpb];
        float yv = tot * su;
        c.ybuf[col] = yv;
        ssq[cl] = yv * yv;
    }
    __syncthreads();
    if (threadIdx.x == 0) {
        float p = 0.0f;
        for (int q = 0; q < cpb; ++q) p += ssq[q];
        g_partY[c.m][c.bg] = p;
    }
}

// Phase Z: ubuf = W v_hat  (v_hat = sv * ybuf). Warp per row, shfl reduce.
__global__ void pi_phaseZ(const float* __restrict__ Win, const float* __restrict__ Wrec,
                          const float* __restrict__ Wout) {
    PiCtx c = pi_ctx(blockIdx.x, Win, Wrec, Wout);
    float ss = 0.0f;
    for (int g = 0; g < c.G; ++g) ss += g_partY[c.m][g];
    float sv = 1.0f / (sqrtf(ss) + EPSN);

    int warp = threadIdx.x >> 5, lane = threadIdx.x & 31;
    int rpb = (c.M + c.G - 1) / c.G;
    int rend = min(c.bg * rpb + rpb, c.M);

    float acc2 = 0.0f;
    for (int r = c.bg * rpb + warp; r < rend; r += 8) {
        const float* row = c.W + (size_t)r * c.N;
        float a = 0.0f;
        for (int j = lane; j < c.N; j += 32) a += row[j] * c.ybuf[j];
        for (int o = 16; o; o >>= 1) a += __shfl_down_sync(0xffffffffu, a, o);
        if (lane == 0) {
            float z = a * sv;
            c.ubuf[r] = z;
            acc2 += z * z;
        }
    }
    __shared__ float wsq[8];
    if (lane == 0) wsq[warp] = acc2;
    __syncthreads();
    if (threadIdx.x == 0) {
        float p = 0.0f;
        for (int w = 0; w < 8; ++w) p += wsq[w];
        g_partZ[c.m][c.bg] = p;
    }
}

// sigma = u_hat . (W v_hat); u_hat = su*ubuf (partZ), v_hat = sv*ybuf (partY).
__global__ void pi_sigma(const float* __restrict__ Win, const float* __restrict__ Wrec,
                         const float* __restrict__ Wout) {
    PiCtx c = pi_ctx(blockIdx.x, Win, Wrec, Wout);
    float ssz = 0.0f, ssy = 0.0f;
    for (int g = 0; g < c.G; ++g) { ssz += g_partZ[c.m][g]; ssy += g_partY[c.m][g]; }
    float su = 1.0f / (sqrtf(ssz) + EPSN);
    float sv = 1.0f / (sqrtf(ssy) + EPSN);

    int warp = threadIdx.x >> 5, lane = threadIdx.x & 31;
    int rpb = (c.M + c.G - 1) / c.G;
    int rend = min(c.bg * rpb + rpb, c.M);

    float contrib = 0.0f;
    for (int r = c.bg * rpb + warp; r < rend; r += 8) {
        const float* row = c.W + (size_t)r * c.N;
        float a = 0.0f;
        for (int j = lane; j < c.N; j += 32) a += row[j] * c.ybuf[j];
        for (int o = 16; o; o >>= 1) a += __shfl_down_sync(0xffffffffu, a, o);
        if (lane == 0) contrib += (su * c.ubuf[r]) * (sv * a);
    }
    __shared__ float wsq[8];
    if (lane == 0) wsq[warp] = contrib;
    __syncthreads();
    if (threadIdx.x == 0) {
        float p = 0.0f;
        for (int w = 0; w < 8; ++w) p += wsq[w];
        g_sigpart[c.m][c.bg] = p;
    }
}

__global__ void pi_finalize() {
    int m = threadIdx.x;
    if (m < 3) {
        int G = (m == 1) ? G_REC : ((m == 0) ? G_IN : G_OUT);
        float s = 0.0f;
        for (int g = 0; g < G; ++g) s += g_sigpart[m][g];
        g_inv_sigma[m] = 1.0f / s;
    }
}

// ---------------------------------------------------------------------------
// SGEMM (NT): C[m,n] = epi( (sum_k A[m,k]*B[n,k]) * inv_sigma[sidx] + bias[n]
//                            [+ add[m,n]] [-> tanh] )
// A: [M,K] row-major. B: [N,K] row-major (contiguous contracted dim).
// 128x128x8 tile, 8x8 per thread, 256 threads.
// Register double-buffer: next k-tile's global loads overlap current compute.
// ---------------------------------------------------------------------------
#define BM 128
#define BN 128
#define BK 8
#define TM 8
#define TN 8

template <bool DO_TANH, bool HAS_ADD>
__global__ __launch_bounds__(256)
void gemm_nt(const float* __restrict__ A, const float* __restrict__ B,
             const float* __restrict__ bias, const float* __restrict__ add,
             float* __restrict__ C, int M, int N, int K, int sidx) {
    __shared__ float As[BK][BM + 4];   // stride 132: conflict-free transposed stores
    __shared__ float Bs[BK][BN + 4];

    int tid = threadIdx.x;
    int bm = blockIdx.y * BM, bn = blockIdx.x * BN;
    int tx = tid & 15, ty = tid >> 4;          // 16x16 thread grid, 8x8 frags
    int lrow = tid >> 1;                        // 0..127
    int lk = (tid & 1) * 4;                     // 0 or 4

    const float* Aptr = A + (size_t)(bm + lrow) * K + lk;
    bool brow_ok = (bn + lrow) < N;
    const float* Bptr = B + (size_t)(bn + lrow) * K + lk;

    float acc[TM][TN];
#pragma unroll
    for (int i = 0; i < TM; ++i)
#pragma unroll
        for (int j = 0; j < TN; ++j) acc[i][j] = 0.0f;

    // preload tile 0
    float4 av = *(const float4*)(Aptr);
    float4 bv = make_float4(0.f, 0.f, 0.f, 0.f);
    if (brow_ok) bv = *(const float4*)(Bptr);

    for (int k0 = 0; k0 < K; k0 += BK) {
        __syncthreads();   // previous tile fully consumed
        As[lk + 0][lrow] = av.x; As[lk + 1][lrow] = av.y;
        As[lk + 2][lrow] = av.z; As[lk + 3][lrow] = av.w;
        Bs[lk + 0][lrow] = bv.x; Bs[lk + 1][lrow] = bv.y;
        Bs[lk + 2][lrow] = bv.z; Bs[lk + 3][lrow] = bv.w;
        __syncthreads();

        // issue next tile's loads; latency hidden by compute below
        if (k0 + BK < K) {
            av = *(const float4*)(Aptr + k0 + BK);
            if (brow_ok) bv = *(const float4*)(Bptr + k0 + BK);
        }

#pragma unroll
        for (int kk = 0; kk < BK; ++kk) {
            float4 a0 = *(const float4*)&As[kk][ty * TM];
            float4 a1 = *(const float4*)&As[kk][ty * TM + 4];
            float4 b0 = *(const float4*)&Bs[kk][tx * TN];
            float4 b1 = *(const float4*)&Bs[kk][tx * TN + 4];
            float ar[TM] = {a0.x, a0.y, a0.z, a0.w, a1.x, a1.y, a1.z, a1.w};
            float br[TN] = {b0.x, b0.y, b0.z, b0.w, b1.x, b1.y, b1.z, b1.w};
#pragma unroll
            for (int i = 0; i < TM; ++i)
#pragma unroll
                for (int j = 0; j < TN; ++j) acc[i][j] += ar[i] * br[j];
        }
    }

    float scale = g_inv_sigma[sidx];
    int row0 = bm + ty * TM, col0 = bn + tx * TN;
#pragma unroll
    for (int i = 0; i < TM; ++i) {
        size_t rbase = (size_t)(row0 + i) * N;
#pragma unroll
        for (int j = 0; j < TN; ++j) {
            int cc = col0 + j;
            if (cc < N) {
                float v = acc[i][j] * scale + bias[cc];
                if (HAS_ADD) v += add[rbase + cc];
                if (DO_TANH) v = tanhf(v);
                C[rbase + cc] = v;
            }
        }
    }
}

// Step 1 (h0 = 0): h = tanh(x_proj + b_rec), elementwise.
__global__ void step1_kernel(const float* __restrict__ xp, const float* __restrict__ brec,
                             float* __restrict__ h) {
    size_t i = ((size_t)blockIdx.x * blockDim.x + threadIdx.x) * 4;
    float4 v = *(const float4*)(xp + i);
    int col = (int)(i & (HID - 1));
    v.x = tanhf(v.x + brec[col + 0]);
    v.y = tanhf(v.y + brec[col + 1]);
    v.z = tanhf(v.z + brec[col + 2]);
    v.w = tanhf(v.w + brec[col + 3]);
    *(float4*)(h + i) = v;
}

// ---------------------------------------------------------------------------
// Launch
// ---------------------------------------------------------------------------
extern "C" void kernel_launch(void* const* d_in, const int* in_sizes, int n_in,
                              void* d_out, int out_size) {
    (void)in_sizes; (void)n_in; (void)out_size;
    const float* x    = (const float*)d_in[0];
    const float* Win  = (const float*)d_in[1];
    const float* bin  = (const float*)d_in[2];
    const float* Wrec = (const float*)d_in[3];
    const float* brec = (const float*)d_in[4];
    const float* Wout = (const float*)d_in[5];
    const float* bout = (const float*)d_in[6];
    float* out = (float*)d_out;

    float *xproj, *h0, *h1;
    cudaGetSymbolAddress((void**)&xproj, g_xproj);
    cudaGetSymbolAddress((void**)&h0, g_h0);
    cudaGetSymbolAddress((void**)&h1, g_h1);

    // --- spectral norms (power iteration, fp32, exact reference sequence) ---
    pi_init<<<1, 256>>>();
    for (int it = 0; it < NPI; ++it) {
        pi_phaseY<<<NB_PI, 256>>>(Win, Wrec, Wout);
        pi_phaseZ<<<NB_PI, 256>>>(Win, Wrec, Wout);
    }
    pi_phaseY<<<NB_PI, 256>>>(Win, Wrec, Wout);   // final v = norm(W^T u)
    pi_sigma<<<NB_PI, 256>>>(Win, Wrec, Wout);    // sigma = u . (W v)
    pi_finalize<<<1, 32>>>();

    // --- x_proj = x @ Win^T / s_in + b_in ---
    gemm_nt<false, false><<<dim3(HID / BN, BATCH / BM), 256>>>(
        x, Win, bin, nullptr, xproj, BATCH, HID, IN_DIM, 0);

    // --- step 1: h = tanh(x_proj + b_rec) (h0 == 0) ---
    step1_kernel<<<(BATCH * HID) / (256 * 4), 256>>>(xproj, brec, h0);

    // --- steps 2..30: h = tanh(x_proj + h @ Wrec^T / s_rec + b_rec) ---
    float* hin = h0;
    float* hout = h1;
    for (int s = 1; s < STEPS; ++s) {
        gemm_nt<true, true><<<dim3(HID / BN, BATCH / BM), 256>>>(
            hin, Wrec, brec, xproj, hout, BATCH, HID, HID, 1);
        float* t = hin; hin = hout; hout = t;
    }

    // --- out = h @ Wout^T / s_out + b_out ---
    gemm_nt<false, false><<<dim3((OUT_DIM + BN - 1) / BN, BATCH / BM), 256>>>(
        hin, Wout, bout, nullptr, out, BATCH, OUT_DIM, HID, 2);
}